// round 3
// baseline (speedup 1.0000x reference)
#include <cuda_runtime.h>

#define NQ      12
#define DIM     4096
#define THREADS 256
// smem buffers sized for the larger of the two skewed layouts:
//  addr1(i) = i + (i>>4)        -> max 4095 + 255 = 4350
//  addr2(i) = i + ((i>>8)<<4)   -> max 4095 + 240 = 4335
#define SMEM_F  4352

__device__ __forceinline__ int addr1(int i) { return i + (i >> 4); }
__device__ __forceinline__ int addr2(int i) { return i + ((i >> 8) << 4); }

// One butterfly sweep on local bit L (compile-time) of the 16 register-resident
// complex amplitudes, using gate q (read via smem broadcast).
template<int L>
__device__ __forceinline__ void sweep(float xr[16], float xi[16], const float2 gq[4])
{
    const float2 g00 = gq[0], g01 = gq[1], g10 = gq[2], g11 = gq[3];
#pragma unroll
    for (int m = 0; m < 8; m++) {
        const int j0 = ((m >> L) << (L + 1)) | (m & ((1 << L) - 1));
        const int j1 = j0 | (1 << L);

        float ar = xr[j0], ai = xi[j0];
        float br = xr[j1], bi = xi[j1];

        xr[j0] = g00.x * ar - g00.y * ai + g01.x * br - g01.y * bi;
        xi[j0] = g00.x * ai + g00.y * ar + g01.x * bi + g01.y * br;
        xr[j1] = g10.x * ar - g10.y * ai + g11.x * br - g11.y * bi;
        xi[j1] = g10.x * ai + g10.y * ar + g11.x * bi + g11.y * br;
    }
}

__global__ __launch_bounds__(THREADS)
void u3_layer_kernel(const float* __restrict__ thetas,
                     const float* __restrict__ re_g,
                     const float* __restrict__ im_g,
                     float2* __restrict__ out)
{
    __shared__ float sre[SMEM_F];
    __shared__ float sim[SMEM_F];
    __shared__ float2 g[NQ][4];   // g00, g01, g10, g11 per gate

    const int b = blockIdx.x;
    const int t = threadIdx.x;

    // ---- 12 U3 gates (one thread each) ----
    if (t < NQ) {
        float th = thetas[t * 3 + 0];
        float ph = thetas[t * 3 + 1];
        float la = thetas[t * 3 + 2];
        float s, c;   sincosf(0.5f * th, &s, &c);
        float sl, cl; sincosf(la, &sl, &cl);
        float sp, cp; sincosf(ph, &sp, &cp);
        float cre = cp * cl - sp * sl;   // e^{i(ph+la)}
        float cim = sp * cl + cp * sl;
        g[t][0] = make_float2(c, 0.0f);
        g[t][1] = make_float2(-cl * s, -sl * s);
        g[t][2] = make_float2(cp * s, sp * s);
        g[t][3] = make_float2(cre * c, cim * c);
    }

    // ---- load layout A: thread t owns global indices [16t, 16t+16) ----
    float xr[16], xi[16];
    {
        const float4* rp = (const float4*)(re_g + (size_t)b * DIM + t * 16);
        const float4* ip = (const float4*)(im_g + (size_t)b * DIM + t * 16);
#pragma unroll
        for (int j = 0; j < 4; j++) {
            float4 r4 = rp[j];
            float4 i4 = ip[j];
            xr[4 * j + 0] = r4.x; xr[4 * j + 1] = r4.y; xr[4 * j + 2] = r4.z; xr[4 * j + 3] = r4.w;
            xi[4 * j + 0] = i4.x; xi[4 * j + 1] = i4.y; xi[4 * j + 2] = i4.z; xi[4 * j + 3] = i4.w;
        }
    }
    __syncthreads();   // gates visible

    // ---- phase A: global bits 0..3 (local j bits). gate for bit p is q = 11-p ----
    sweep<0>(xr, xi, g[11]);
    sweep<1>(xr, xi, g[10]);
    sweep<2>(xr, xi, g[9]);
    sweep<3>(xr, xi, g[8]);

    // ---- transpose A -> C through smem (skew addr1, conflict-free) ----
#pragma unroll
    for (int j = 0; j < 16; j++) {
        int i = t * 16 + j;
        int a = addr1(i);
        sre[a] = xr[j]; sim[a] = xi[j];
    }
    __syncthreads();
    const int hi = t >> 4, lo = t & 15;
#pragma unroll
    for (int j = 0; j < 16; j++) {
        int i = hi * 256 + j * 16 + lo;   // local j = global bits 4..7
        int a = addr1(i);
        xr[j] = sre[a]; xi[j] = sim[a];
    }

    // ---- phase C: global bits 4..7 -> gates 7,6,5,4 ----
    sweep<0>(xr, xi, g[7]);
    sweep<1>(xr, xi, g[6]);
    sweep<2>(xr, xi, g[5]);
    sweep<3>(xr, xi, g[4]);

    __syncthreads();   // WAR: everyone done reading before rewrite

    // ---- transpose C -> B through smem (skew addr2, conflict-free) ----
#pragma unroll
    for (int j = 0; j < 16; j++) {
        int i = hi * 256 + j * 16 + lo;
        int a = addr2(i);
        sre[a] = xr[j]; sim[a] = xi[j];
    }
    __syncthreads();
#pragma unroll
    for (int j = 0; j < 16; j++) {
        int i = t + 256 * j;              // local j = global bits 8..11
        int a = addr2(i);
        xr[j] = sre[a]; xi[j] = sim[a];
    }

    // ---- phase B: global bits 8..11 -> gates 3,2,1,0 ----
    sweep<0>(xr, xi, g[3]);
    sweep<1>(xr, xi, g[2]);
    sweep<2>(xr, xi, g[1]);
    sweep<3>(xr, xi, g[0]);

    // ---- store: layout B gives perfectly coalesced float2 writes ----
    float2* o = out + (size_t)b * DIM;
#pragma unroll
    for (int j = 0; j < 16; j++) {
        o[t + 256 * j] = make_float2(xr[j], xi[j]);
    }
}

extern "C" void kernel_launch(void* const* d_in, const int* in_sizes, int n_in,
                              void* d_out, int out_size)
{
    // thetas is the 36-element input; the two DIM*BATCH inputs are
    // state_re then state_im in metadata order.
    int ti = -1, ri = -1, ii = -1;
    for (int k = 0; k < n_in; k++) {
        if (in_sizes[k] == NQ * 3) { ti = k; }
        else if (ri < 0)           { ri = k; }
        else                       { ii = k; }
    }
    const float* thetas = (const float*)d_in[ti];
    const float* re     = (const float*)d_in[ri];
    const float* im     = (const float*)d_in[ii];
    float2* out = (float2*)d_out;

    int batch = in_sizes[ri] / DIM;  // 512
    u3_layer_kernel<<<batch, THREADS>>>(thetas, re, im, out);
}